// round 7
// baseline (speedup 1.0000x reference)
#include <cuda_runtime.h>
#include <stdint.h>

// HSTUBlockPreprocessor: jagged concat of [ctx1 | ctx2 | interleave(item, action)]
// per sample, plus merged lengths appended after the values.
// Persistent grid-stride version: exactly-resident grid, no wave tail.

#define HSTU_D 512
#define ROW_VEC (HSTU_D / 4)        // 128 float4 per row
#define ROWS_PER_BLOCK 8
#define THREADS 256
#define ROWS_PER_THREAD 4           // each thread loads 4 float4s (one per row)
#define GRID_BLOCKS (148 * 8)       // full residency on 148-SM sm_100a

__device__ __forceinline__ int comp_off(const int* __restrict__ item_off,
                                        const int* __restrict__ ctx1_off,
                                        const int* __restrict__ ctx2_off,
                                        int b)
{
    return ctx1_off[b] + ctx2_off[b] + 2 * item_off[b];
}

__global__ void __launch_bounds__(THREADS)
hstu_gather_rows(const float* __restrict__ item,
                 const float* __restrict__ action,
                 const float* __restrict__ ctx1,
                 const float* __restrict__ ctx2,
                 const int* __restrict__ item_off,
                 const int* __restrict__ ctx1_off,
                 const int* __restrict__ ctx2_off,
                 float* __restrict__ out,
                 int B, int total_rows, int n_tiles, int write_lengths)
{
    const int tid = threadIdx.x;

    // ---- block 0 also writes merged lengths (tiny; overlaps with copy work) ----
    if (blockIdx.x == 0 && write_lengths && tid < B) {
        int len = (ctx1_off[tid + 1] - ctx1_off[tid])
                + (ctx2_off[tid + 1] - ctx2_off[tid])
                + 2 * (item_off[tid + 1] - item_off[tid]);
        out[(size_t)total_rows * HSTU_D + tid] = (float)len;
    }

    const int lane = tid & (ROW_VEC - 1);
    const int half = tid >> 7;            // 0 or 1: which 4-row group

    for (int tile = blockIdx.x; tile < n_tiles; tile += gridDim.x) {
        const int row0 = tile * ROWS_PER_BLOCK;

        // ---- sample lookup: parallel count (B <= 256 = blockDim).
        //      One independent load + one barrier; b = count - 1 (comp_off(0)==0).
        int b;
        {
            __syncthreads();   // protect re-use across loop iterations
            int pred = (tid < B) ? (comp_off(item_off, ctx1_off, ctx2_off, tid) <= row0) : 0;
            b = __syncthreads_count(pred) - 1;
        }

        // ---- metadata for sample b and (possibly) b+1; a tile spans <= 2
        //      samples since min segment length (2*128+1+2 = 259) >> 8. ----
        const int nb = (b + 1 < B) ? comp_off(item_off, ctx1_off, ctx2_off, b + 1)
                                   : 0x7fffffff;

        const int i0a  = item_off[b];
        const int c1oa = ctx1_off[b];
        const int c2oa = ctx2_off[b];
        const int c1a  = ctx1_off[b + 1] - c1oa;
        const int c2a  = ctx2_off[b + 1] - c2oa;

        const int bn   = (b + 1 < B) ? (b + 1) : b;
        const int i0b  = item_off[bn];
        const int c1ob = ctx1_off[bn];
        const int c2ob = ctx2_off[bn];
        const int c1b  = ctx1_off[bn + 1] - c1ob;
        const int c2b  = ctx2_off[bn + 1] - c2ob;

        const int rbase = row0 + half * ROWS_PER_THREAD;

        const float4* __restrict__ src4[ROWS_PER_THREAD];
        bool valid[ROWS_PER_THREAD];

        #pragma unroll
        for (int k = 0; k < ROWS_PER_THREAD; k++) {
            const int row = rbase + k;
            valid[k] = (row < total_rows);

            const bool adv = (row >= nb);
            const int i0  = adv ? i0b  : i0a;
            const int c1o = adv ? c1ob : c1oa;
            const int c2o = adv ? c2ob : c2oa;
            const int c1  = adv ? c1b  : c1a;
            const int c2  = adv ? c2b  : c2a;

            const int r = row - (c1o + c2o + 2 * i0);

            const float* src;
            if (r < c1) {
                src = ctx1 + (size_t)(c1o + r) * HSTU_D;
            } else if (r < c1 + c2) {
                src = ctx2 + (size_t)(c2o + (r - c1)) * HSTU_D;
            } else {
                const int t = r - c1 - c2;        // position in interleaved segment
                const int i = i0 + (t >> 1);      // item/action row index
                src = ((t & 1) ? action : item) + (size_t)i * HSTU_D;
            }
            src4[k] = (const float4*)src;
        }

        // Front-batched loads (MLP=4 per thread), then stores.
        float4 v[ROWS_PER_THREAD];
        #pragma unroll
        for (int k = 0; k < ROWS_PER_THREAD; k++)
            if (valid[k]) v[k] = __ldg(&src4[k][lane]);

        float4* __restrict__ d4 = (float4*)(out + (size_t)rbase * HSTU_D);
        #pragma unroll
        for (int k = 0; k < ROWS_PER_THREAD; k++)
            if (valid[k]) d4[(size_t)k * ROW_VEC + lane] = v[k];
    }
}

extern "C" void kernel_launch(void* const* d_in, const int* in_sizes, int n_in,
                              void* d_out, int out_size)
{
    const float* item   = (const float*)d_in[0];
    const float* action = (const float*)d_in[1];
    const float* ctx1   = (const float*)d_in[2];
    const float* ctx2   = (const float*)d_in[3];
    const int* item_off = (const int*)d_in[4];
    const int* ctx1_off = (const int*)d_in[5];
    const int* ctx2_off = (const int*)d_in[6];
    float* out = (float*)d_out;

    const int B = in_sizes[4] - 1;
    const long long total_vals = 2LL * in_sizes[0] + in_sizes[2] + in_sizes[3];
    const int total_rows = (int)(total_vals / HSTU_D);

    const int n_tiles = (total_rows + ROWS_PER_BLOCK - 1) / ROWS_PER_BLOCK;
    const int write_lengths = ((long long)out_size >= total_vals + B) ? 1 : 0;
    const int grid = (n_tiles < GRID_BLOCKS) ? n_tiles : GRID_BLOCKS;

    hstu_gather_rows<<<grid, THREADS>>>(item, action, ctx1, ctx2,
                                        item_off, ctx1_off, ctx2_off,
                                        out, B, total_rows, n_tiles, write_lengths);
}

// round 8
// speedup vs baseline: 1.0556x; 1.0556x over previous
#include <cuda_runtime.h>
#include <stdint.h>

// HSTUBlockPreprocessor: jagged concat of [ctx1 | ctx2 | interleave(item, action)]
// per sample, plus merged lengths appended after the values.
// R5 configuration (best measured): 256 threads/block, 8 rows/block, MLP=4/thread,
// ballot-based sample lookup, lengths write fused as tail block.

#define HSTU_D 512
#define ROW_VEC (HSTU_D / 4)        // 128 float4 per row
#define ROWS_PER_BLOCK 8
#define THREADS 256
#define ROWS_PER_THREAD 4           // each thread loads 4 float4s (one per row)

__device__ __forceinline__ int comp_off(const int* __restrict__ item_off,
                                        const int* __restrict__ ctx1_off,
                                        const int* __restrict__ ctx2_off,
                                        int b)
{
    return ctx1_off[b] + ctx2_off[b] + 2 * item_off[b];
}

__global__ void __launch_bounds__(THREADS)
hstu_gather_rows(const float* __restrict__ item,
                 const float* __restrict__ action,
                 const float* __restrict__ ctx1,
                 const float* __restrict__ ctx2,
                 const int* __restrict__ item_off,
                 const int* __restrict__ ctx1_off,
                 const int* __restrict__ ctx2_off,
                 float* __restrict__ out,
                 int B, int total_rows, int n_copy_blocks)
{
    const int tid = threadIdx.x;

    // ---- tail block: write merged lengths ----
    if (blockIdx.x >= (unsigned)n_copy_blocks) {
        if (tid < B) {
            int len = (ctx1_off[tid + 1] - ctx1_off[tid])
                    + (ctx2_off[tid + 1] - ctx2_off[tid])
                    + 2 * (item_off[tid + 1] - item_off[tid]);
            out[(size_t)total_rows * HSTU_D + tid] = (float)len;
        }
        return;
    }

    const int row0 = blockIdx.x * ROWS_PER_BLOCK;

    // ---- sample lookup: parallel count (one independent load + one barrier).
    //      b = (# samples with comp_off <= row0) - 1; comp_off(0)==0 so count>=1.
    int b;
    if (B <= THREADS) {
        int pred = (tid < B) ? (comp_off(item_off, ctx1_off, ctx2_off, tid) <= row0) : 0;
        b = __syncthreads_count(pred) - 1;
    } else {
        int lo = 0, hi = B - 1;
        while (lo < hi) {
            int mid = (lo + hi + 1) >> 1;
            if (comp_off(item_off, ctx1_off, ctx2_off, mid) <= row0) lo = mid;
            else hi = mid - 1;
        }
        b = lo;
    }

    // ---- metadata for sample b and (possibly) b+1; block spans <= 2 samples
    //      since min segment length (2*128+1+2 = 259) >> ROWS_PER_BLOCK. ----
    const int nb = (b + 1 < B) ? comp_off(item_off, ctx1_off, ctx2_off, b + 1) : 0x7fffffff;

    const int i0a  = item_off[b];
    const int c1oa = ctx1_off[b];
    const int c2oa = ctx2_off[b];
    const int c1a  = ctx1_off[b + 1] - c1oa;
    const int c2a  = ctx2_off[b + 1] - c2oa;

    const int bn   = (b + 1 < B) ? (b + 1) : b;
    const int i0b  = item_off[bn];
    const int c1ob = ctx1_off[bn];
    const int c2ob = ctx2_off[bn];
    const int c1b  = ctx1_off[bn + 1] - c1ob;
    const int c2b  = ctx2_off[bn + 1] - c2ob;

    // Thread t: float4 column (t & 127) of rows row0 + 4*(t>>7) + k, k=0..3.
    const int lane  = tid & (ROW_VEC - 1);
    const int rbase = row0 + (tid >> 7) * ROWS_PER_THREAD;

    const float4* __restrict__ src4[ROWS_PER_THREAD];
    bool valid[ROWS_PER_THREAD];

    #pragma unroll
    for (int k = 0; k < ROWS_PER_THREAD; k++) {
        const int row = rbase + k;
        valid[k] = (row < total_rows);

        const bool adv = (row >= nb);
        const int i0  = adv ? i0b  : i0a;
        const int c1o = adv ? c1ob : c1oa;
        const int c2o = adv ? c2ob : c2oa;
        const int c1  = adv ? c1b  : c1a;
        const int c2  = adv ? c2b  : c2a;

        const int r = row - (c1o + c2o + 2 * i0);

        const float* src;
        if (r < c1) {
            src = ctx1 + (size_t)(c1o + r) * HSTU_D;
        } else if (r < c1 + c2) {
            src = ctx2 + (size_t)(c2o + (r - c1)) * HSTU_D;
        } else {
            const int t = r - c1 - c2;            // position in interleaved segment
            const int i = i0 + (t >> 1);          // item/action row index
            src = ((t & 1) ? action : item) + (size_t)i * HSTU_D;
        }
        src4[k] = (const float4*)src;
    }

    // Front-batched loads (MLP=4 per thread, 8 rows in flight per block).
    float4 v[ROWS_PER_THREAD];
    #pragma unroll
    for (int k = 0; k < ROWS_PER_THREAD; k++)
        if (valid[k]) v[k] = __ldg(&src4[k][lane]);

    float4* __restrict__ d4 = (float4*)(out + (size_t)rbase * HSTU_D);
    #pragma unroll
    for (int k = 0; k < ROWS_PER_THREAD; k++)
        if (valid[k]) d4[(size_t)k * ROW_VEC + lane] = v[k];
}

extern "C" void kernel_launch(void* const* d_in, const int* in_sizes, int n_in,
                              void* d_out, int out_size)
{
    const float* item   = (const float*)d_in[0];
    const float* action = (const float*)d_in[1];
    const float* ctx1   = (const float*)d_in[2];
    const float* ctx2   = (const float*)d_in[3];
    const int* item_off = (const int*)d_in[4];
    const int* ctx1_off = (const int*)d_in[5];
    const int* ctx2_off = (const int*)d_in[6];
    float* out = (float*)d_out;

    const int B = in_sizes[4] - 1;
    const long long total_vals = 2LL * in_sizes[0] + in_sizes[2] + in_sizes[3];
    const int total_rows = (int)(total_vals / HSTU_D);

    const int n_copy_blocks = (total_rows + ROWS_PER_BLOCK - 1) / ROWS_PER_BLOCK;
    const bool write_lengths = ((long long)out_size >= total_vals + B);
    const int grid = n_copy_blocks + (write_lengths ? 1 : 0);

    hstu_gather_rows<<<grid, THREADS>>>(item, action, ctx1, ctx2,
                                        item_off, ctx1_off, ctx2_off,
                                        out, B, total_rows, n_copy_blocks);
}